// round 15
// baseline (speedup 1.0000x reference)
#include <cuda_runtime.h>

// BioSelfAttention — fused, closed-form LIF, single-barrier front end,
// exact all-zero fast exit.
//
// Pipeline: QK dots -> LIF -> WTA(T=128) -> r*V -> LIF -> WTA(T*D=8192).
// One block per (b,h) slice (B*H = 32), 1024 threads.
//
// WTA step: x_i <- clip(3*x_i - 0.9*S, 0, 1), S = sum x (W = inh + (exc-inh)I).
// Exact fixed points => bitwise-stationary early exit is numerically exact.
// LIF closed form: spikes periodic, t1 = ceil(ln(1-1/J)/ln 0.95),
// count over 100 steps = floor(100/t1). Rates feed only the saturated WTA,
// so __logf's ulp-level error (at worst one spike at a ceil boundary) cannot
// change the WTA fixed point.

#define NBH 32

__device__ __forceinline__ float lif_rate_cf(float J) {
    if (J <= 1.0f) return 0.0f;                      // v_inf = J < 1: no spike
    float ratio = __logf(1.0f - 1.0f / J) * (-19.4957257f);  // 1/ln(0.95)
    if (!(ratio <= 100.0f)) return 0.0f;             // no spike in 100 steps
    int t1 = (int)ceilf(ratio);
    if (t1 < 1) t1 = 1;
    return (float)(100 / t1) * 0.01f;                // floor(100/t1)/100
}

__global__ void __launch_bounds__(1024)
k_bio_fused(const float* __restrict__ Q, const float* __restrict__ K,
            const float* __restrict__ V, float* __restrict__ out) {
    const int tid  = threadIdx.x;
    const int wid  = tid >> 5;     // 0..31
    const int lane = tid & 31;

    __shared__ float sR[128];      // token rates
    __shared__ float sw[32];       // stage-E per-warp sums

    const size_t base = (size_t)blockIdx.x * 8192;
    const float* Qb = Q + base;
    const float* Kb = K + base;
    const float* Vb = V + base;
    float*       Ob = out + base;

    // ---- Stage A+B: warp w owns tokens 4w..4w+3; 8 lanes per token, each
    //      lane covers 8 columns (2 float4 of Q + 2 of K, front-batched).
    //      3-level shfl_xor inside each 8-lane group completes the dot; the
    //      group leader runs the closed-form LIF. ONE block barrier total. ----
    {
        const int tok = (wid << 2) + (lane >> 3);    // this lane's token
        const int f4  = (lane & 7) << 1;             // float4 index 0,2,..,14
        const float4* qr = reinterpret_cast<const float4*>(Qb + tok * 64);
        const float4* kr = reinterpret_cast<const float4*>(Kb + tok * 64);
        float4 q0 = qr[f4], q1 = qr[f4 + 1];
        float4 k0 = kr[f4], k1 = kr[f4 + 1];
        float a = q0.x * k0.x;
        a = fmaf(q0.y, k0.y, a); a = fmaf(q0.z, k0.z, a); a = fmaf(q0.w, k0.w, a);
        a = fmaf(q1.x, k1.x, a); a = fmaf(q1.y, k1.y, a);
        a = fmaf(q1.z, k1.z, a); a = fmaf(q1.w, k1.w, a);
        // reduce within each 8-lane group (stays inside the group for off<8)
        a += __shfl_xor_sync(0xffffffffu, a, 4);
        a += __shfl_xor_sync(0xffffffffu, a, 2);
        a += __shfl_xor_sync(0xffffffffu, a, 1);
        if ((lane & 7) == 0)                         // no syncs inside branch
            sR[tok] = lif_rate_cf(a);
    }
    __syncthreads();

    // ---- Stage C: WTA over T=128, computed redundantly in EVERY warp
    //      (identical data + ops -> bitwise-identical y, NO barriers). ----
    float y[4];
    #pragma unroll
    for (int j = 0; j < 4; ++j) y[j] = sR[lane + 32 * j];

    for (int it = 0; it < 20; ++it) {
        float l = (y[0] + y[1]) + (y[2] + y[3]);
        #pragma unroll
        for (int off = 16; off; off >>= 1)
            l += __shfl_xor_sync(0xffffffffu, l, off);
        if (l == 0.0f) break;                       // S=0: identity for y in [0,1]
        bool same = true;
        #pragma unroll
        for (int j = 0; j < 4; ++j) {
            float ny = fminf(fmaxf(fmaf(3.0f, y[j], -0.9f * l), 0.0f), 1.0f);
            same &= (ny == y[j]);
            y[j] = ny;
        }
        if (__all_sync(0xffffffffu, same)) break;   // exact fixed point
    }

    // ---- Fast exit: all rates zero (block-uniform, warp-local test).
    //      Zero rates => J_v = 0 => z = 0 is stage E's exact fixed point. ----
    {
        bool z4 = (y[0] == 0.0f) & (y[1] == 0.0f) & (y[2] == 0.0f) & (y[3] == 0.0f);
        if (__all_sync(0xffffffffu, z4)) {
            float4 zero4 = make_float4(0.f, 0.f, 0.f, 0.f);
            float4* o4 = reinterpret_cast<float4*>(Ob);
            o4[tid]        = zero4;                  // 2 coalesced STG.128
            o4[tid + 1024] = zero4;
            return;
        }
    }

    // ---- Stage D: J_v = rate * V, closed-form LIF. Warp w owns tokens
    //      {w, w+32, w+64, w+96}, 2 elems/lane. Shfl unconditional; zero-rate
    //      tokens skip the V load (warp-uniform branch). ----
    float z[4][2];
    #pragma unroll
    for (int j = 0; j < 4; ++j) {
        float r = __shfl_sync(0xffffffffu, y[j], wid);  // rate of token w+32j
        if (r != 0.0f) {
            int tok = wid + 32 * j;
            float2 v2 = reinterpret_cast<const float2*>(Vb + tok * 64)[lane];
            z[j][0] = lif_rate_cf(r * v2.x);
            z[j][1] = lif_rate_cf(r * v2.y);
        } else {
            z[j][0] = 0.0f;
            z[j][1] = 0.0f;
        }
    }

    // ---- Stage E: WTA over T*D=8192, block-wide, 8 values/thread. ----
    for (int it = 0; it < 20; ++it) {
        float l = ((z[0][0] + z[0][1]) + (z[1][0] + z[1][1]))
                + ((z[2][0] + z[2][1]) + (z[3][0] + z[3][1]));
        #pragma unroll
        for (int off = 16; off; off >>= 1)
            l += __shfl_xor_sync(0xffffffffu, l, off);
        if (lane == 0) sw[wid] = l;
        __syncthreads();
        float S = sw[lane];
        #pragma unroll
        for (int off = 16; off; off >>= 1)
            S += __shfl_xor_sync(0xffffffffu, S, off);
        if (S == 0.0f) break;            // all-zero: exact fixed point (uniform)
        int same = 1;
        #pragma unroll
        for (int j = 0; j < 4; ++j)
            #pragma unroll
            for (int k = 0; k < 2; ++k) {
                float nz = fminf(fmaxf(fmaf(3.0f, z[j][k], -0.9f * S), 0.0f), 1.0f);
                same &= (nz == z[j][k]);
                z[j][k] = nz;
            }
        if (__syncthreads_and(same)) break;   // barrier + block-uniform vote
    }

    // ---- Store: coalesced float2 per lane, token-major. ----
    #pragma unroll
    for (int j = 0; j < 4; ++j) {
        int tok = wid + 32 * j;
        reinterpret_cast<float2*>(Ob + tok * 64)[lane] = make_float2(z[j][0], z[j][1]);
    }
}

extern "C" void kernel_launch(void* const* d_in, const int* in_sizes, int n_in,
                              void* d_out, int out_size) {
    const float* Q = (const float*)d_in[0];
    const float* K = (const float*)d_in[1];
    const float* V = (const float*)d_in[2];
    k_bio_fused<<<NBH, 1024>>>(Q, K, V, (float*)d_out);
}

// round 16
// speedup vs baseline: 1.0435x; 1.0435x over previous
#include <cuda_runtime.h>

// BioSelfAttention — fused, closed-form LIF, exact all-zero fast exit.
// R14 structure (measured best: smem-partial dot front end) + __logf.
//
// Pipeline: QK dots -> LIF -> WTA(T=128) -> r*V -> LIF -> WTA(T*D=8192).
// One block per (b,h) slice (B*H = 32), 1024 threads.
//
// WTA step: x_i <- clip(3*x_i - 0.9*S, 0, 1), S = sum x (W = inh + (exc-inh)I).
// Exact fixed points => bitwise-stationary early exit is numerically exact.
// LIF closed form: spikes periodic, t1 = ceil(ln(1-1/J)/ln 0.95),
// count over 100 steps = floor(100/t1). Rates feed only the massively
// saturated WTA, so __logf's ulp-level error (at worst one spike at a ceil
// boundary) cannot change the WTA fixed point.
//
// Fast exit: stage C's y is bitwise-identical in every warp, so "all rates
// zero" is a block-uniform predicate evaluable without a barrier. Zero rates
// => J_v = 0 => z = 0, which is stage E's exact fixed point => output is
// exactly zero; store zeros and return.

#define NBH 32

__device__ __forceinline__ float lif_rate_cf(float J) {
    if (J <= 1.0f) return 0.0f;                      // v_inf = J < 1: no spike
    float ratio = __logf(1.0f - 1.0f / J) * (-19.4957257f);  // 1/ln(0.95)
    if (!(ratio <= 100.0f)) return 0.0f;             // no spike in 100 steps
    int t1 = (int)ceilf(ratio);
    if (t1 < 1) t1 = 1;
    return (float)(100 / t1) * 0.01f;                // floor(100/t1)/100
}

__global__ void __launch_bounds__(1024)
k_bio_fused(const float* __restrict__ Q, const float* __restrict__ K,
            const float* __restrict__ V, float* __restrict__ out) {
    const int tid  = threadIdx.x;
    const int wid  = tid >> 5;     // 0..31
    const int lane = tid & 31;

    __shared__ float sP[1024];     // stage-A partial dots
    __shared__ float sR[128];      // token rates
    __shared__ float sw[32];       // stage-E per-warp sums

    const size_t base = (size_t)blockIdx.x * 8192;
    const float* Qb = Q + base;
    const float* Kb = K + base;
    const float* Vb = V + base;
    float*       Ob = out + base;

    // ---- Stage A: QK partial dots, SHFL-free. 8 threads per token, each
    //      owns 8 consecutive columns (2 float4 of Q + 2 of K, coalesced,
    //      all four LDG.128 front-batched). ----
    {
        const int tok = tid >> 3;
        const int f4  = (tid & 7) << 1;
        const float4* qr = reinterpret_cast<const float4*>(Qb + tok * 64);
        const float4* kr = reinterpret_cast<const float4*>(Kb + tok * 64);
        float4 q0 = qr[f4], q1 = qr[f4 + 1];
        float4 k0 = kr[f4], k1 = kr[f4 + 1];
        float a = q0.x * k0.x;
        a = fmaf(q0.y, k0.y, a); a = fmaf(q0.z, k0.z, a); a = fmaf(q0.w, k0.w, a);
        a = fmaf(q1.x, k1.x, a); a = fmaf(q1.y, k1.y, a);
        a = fmaf(q1.z, k1.z, a); a = fmaf(q1.w, k1.w, a);
        sP[tid] = a;
    }
    __syncthreads();

    // ---- Stage B: 128 threads finish the dots (2 LDS.128) + closed-form LIF. ----
    if (tid < 128) {
        const float4* p = reinterpret_cast<const float4*>(sP) + (tid << 1);
        float4 p0 = p[0], p1 = p[1];
        float J = ((p0.x + p0.y) + (p0.z + p0.w)) + ((p1.x + p1.y) + (p1.z + p1.w));
        sR[tid] = lif_rate_cf(J);
    }
    __syncthreads();

    // ---- Stage C: WTA over T=128, computed redundantly in EVERY warp
    //      (identical data + ops -> bitwise-identical y, NO barriers). ----
    float y[4];
    #pragma unroll
    for (int j = 0; j < 4; ++j) y[j] = sR[lane + 32 * j];

    for (int it = 0; it < 20; ++it) {
        float l = (y[0] + y[1]) + (y[2] + y[3]);
        #pragma unroll
        for (int off = 16; off; off >>= 1)
            l += __shfl_xor_sync(0xffffffffu, l, off);
        if (l == 0.0f) break;                       // S=0: identity for y in [0,1]
        bool same = true;
        #pragma unroll
        for (int j = 0; j < 4; ++j) {
            float ny = fminf(fmaxf(fmaf(3.0f, y[j], -0.9f * l), 0.0f), 1.0f);
            same &= (ny == y[j]);
            y[j] = ny;
        }
        if (__all_sync(0xffffffffu, same)) break;   // exact fixed point
    }

    // ---- Fast exit: all rates zero (block-uniform, warp-local test). ----
    {
        bool z4 = (y[0] == 0.0f) & (y[1] == 0.0f) & (y[2] == 0.0f) & (y[3] == 0.0f);
        if (__all_sync(0xffffffffu, z4)) {
            float4 zero4 = make_float4(0.f, 0.f, 0.f, 0.f);
            float4* o4 = reinterpret_cast<float4*>(Ob);
            o4[tid]        = zero4;                  // 2 coalesced STG.128
            o4[tid + 1024] = zero4;
            return;
        }
    }

    // ---- Stage D: J_v = rate * V, closed-form LIF. Warp w owns tokens
    //      {w, w+32, w+64, w+96}, 2 elems/lane. Shfl unconditional; zero-rate
    //      tokens skip the V load (warp-uniform branch). ----
    float z[4][2];
    #pragma unroll
    for (int j = 0; j < 4; ++j) {
        float r = __shfl_sync(0xffffffffu, y[j], wid);  // rate of token w+32j
        if (r != 0.0f) {
            int tok = wid + 32 * j;
            float2 v2 = reinterpret_cast<const float2*>(Vb + tok * 64)[lane];
            z[j][0] = lif_rate_cf(r * v2.x);
            z[j][1] = lif_rate_cf(r * v2.y);
        } else {
            z[j][0] = 0.0f;
            z[j][1] = 0.0f;
        }
    }

    // ---- Stage E: WTA over T*D=8192, block-wide, 8 values/thread. ----
    for (int it = 0; it < 20; ++it) {
        float l = ((z[0][0] + z[0][1]) + (z[1][0] + z[1][1]))
                + ((z[2][0] + z[2][1]) + (z[3][0] + z[3][1]));
        #pragma unroll
        for (int off = 16; off; off >>= 1)
            l += __shfl_xor_sync(0xffffffffu, l, off);
        if (lane == 0) sw[wid] = l;
        __syncthreads();
        float S = sw[lane];
        #pragma unroll
        for (int off = 16; off; off >>= 1)
            S += __shfl_xor_sync(0xffffffffu, S, off);
        if (S == 0.0f) break;            // all-zero: exact fixed point (uniform)
        int same = 1;
        #pragma unroll
        for (int j = 0; j < 4; ++j)
            #pragma unroll
            for (int k = 0; k < 2; ++k) {
                float nz = fminf(fmaxf(fmaf(3.0f, z[j][k], -0.9f * S), 0.0f), 1.0f);
                same &= (nz == z[j][k]);
                z[j][k] = nz;
            }
        if (__syncthreads_and(same)) break;   // barrier + block-uniform vote
    }

    // ---- Store: coalesced float2 per lane, token-major. ----
    #pragma unroll
    for (int j = 0; j < 4; ++j) {
        int tok = wid + 32 * j;
        reinterpret_cast<float2*>(Ob + tok * 64)[lane] = make_float2(z[j][0], z[j][1]);
    }
}

extern "C" void kernel_launch(void* const* d_in, const int* in_sizes, int n_in,
                              void* d_out, int out_size) {
    const float* Q = (const float*)d_in[0];
    const float* K = (const float*)d_in[1];
    const float* V = (const float*)d_in[2];
    k_bio_fused<<<NBH, 1024>>>(Q, K, V, (float*)d_out);
}